// round 17
// baseline (speedup 1.0000x reference)
#include <cuda_runtime.h>
#include <math.h>
#include <stdint.h>

#define BQ    32
#define CIN   128
#define LIN   1024
#define NE    4
#define COUT  128
#define KW    64
#define LOUT  961          // 1024 - 64 + 1
#define NTILE 56
#define NTILES 18          // 18*56 = 1008 >= 961; 576 CTAs, 2/SM -> 1.95 waves
// pre-swizzled A fragments: [e][c][warp(8)][kk(4)][lane(32)][q(4)] uint32
#define ACH   (8 * 4 * 32 * 4)          // words per (e,c) = 4096 (16KB)
// B rows: sxq[ch][bb][j], bb=0..13, j=0..13, row stride 20 words (80B:
// 16B-aligned for LDS.128, bb*20 mod 32 distinct per quarter-warp phase)
#define BROW  20
#define BCH   (14 * BROW)               // 280 words per channel
#define BBUF  (4 * BCH)                 // 1120 words per 4-channel group buffer
#define NENT  (4 * 196)                 // 784 packed entries per group

// ---------------- scratch (device globals: no allocation allowed) ----------
__device__ float    g_gatex[BQ * CIN];
__device__ int      g_sel [BQ * 2];
__device__ float    g_selw[BQ * 2];
__device__ uint32_t g_w1h[NE * CIN * ACH];   // fragment-ordered f16x2 W1, 8.4MB

// ---------------- helpers -------------------------------------------------
__device__ __forceinline__ uint32_t pack_f16x2(float lo, float hi) {
    uint32_t r;
    asm("cvt.rn.f16x2.f32 %0, %1, %2;" : "=r"(r) : "f"(hi), "f"(lo));
    return r;
}

__device__ __forceinline__ void mma_f16(float* c,
                                        uint32_t a0, uint32_t a1, uint32_t a2, uint32_t a3,
                                        uint32_t b0, uint32_t b1) {
    asm volatile("mma.sync.aligned.m16n8k16.row.col.f32.f16.f16.f32 "
                 "{%0,%1,%2,%3}, {%4,%5,%6,%7}, {%8,%9}, {%0,%1,%2,%3};"
                 : "+f"(c[0]), "+f"(c[1]), "+f"(c[2]), "+f"(c[3])
                 : "r"(a0), "r"(a1), "r"(a2), "r"(a3), "r"(b0), "r"(b1));
}

// One channel's 28 MMAs: A fragments register-direct; B row loaded as
// 4 x LDS.128 (words 14,15 of the padded row are unused).
__device__ __forceinline__ void mma_channel(float acc[7][4],
                                            uint4 A0, uint4 A1, uint4 A2, uint4 A3,
                                            const uint32_t* __restrict__ row)
{
    uint32_t P[16];
    *(uint4*)&P[0]  = *(const uint4*)(row + 0);
    *(uint4*)&P[4]  = *(const uint4*)(row + 4);
    *(uint4*)&P[8]  = *(const uint4*)(row + 8);
    *(uint4*)&P[12] = *(const uint4*)(row + 12);
#pragma unroll
    for (int nb = 0; nb < 7; ++nb)
        mma_f16(acc[nb], A0.x, A0.y, A0.z, A0.w, P[nb],     P[nb + 1]);
#pragma unroll
    for (int nb = 0; nb < 7; ++nb)
        mma_f16(acc[nb], A1.x, A1.y, A1.z, A1.w, P[nb + 2], P[nb + 3]);
#pragma unroll
    for (int nb = 0; nb < 7; ++nb)
        mma_f16(acc[nb], A2.x, A2.y, A2.z, A2.w, P[nb + 4], P[nb + 5]);
#pragma unroll
    for (int nb = 0; nb < 7; ++nb)
        mma_f16(acc[nb], A3.x, A3.y, A3.z, A3.w, P[nb + 6], P[nb + 7]);
}

// load one channel's A fragments (4 x LDG.128) into named uint4 regs
#define LDA(R0, R1, R2, R3, CHN) do {                                          \
        const uint4* ap_ = (const uint4*)(Ae + (size_t)(CHN) * ACH);           \
        R0 = ap_[0]; R1 = ap_[32]; R2 = ap_[64]; R3 = ap_[96];                 \
    } while (0)

// load x regs for 4-channel group G (entries tid, tid+256, tid+512, tid+768)
#define LDX(G) do {                                                            \
        _Pragma("unroll")                                                      \
        for (int i_ = 0; i_ < 4; ++i_) if (eact[i_]) {                         \
            const float* xc_ = xb + (size_t)(4 * (G) + ech[i_]) * LIN          \
                               + (l0 + epos[i_]);                              \
            xra[i_] = xc_[0];                                                  \
            xrb[i_] = xc_[1];                                                  \
        }                                                                      \
    } while (0)

// store staged x regs into group buffer BUF (literal 0/1)
#define STX(BUF) do {                                                          \
        _Pragma("unroll")                                                      \
        for (int i_ = 0; i_ < 4; ++i_) if (eact[i_])                           \
            sxq[BUF][esmo[i_]] = pack_f16x2(xra[i_], xrb[i_]);                 \
    } while (0)

// ---------------- kernel 0: W1 fp32 -> per-lane A fragments ---------------
__global__ void k_wconv(const float* __restrict__ W1) {
    int idx  = blockIdx.x * 256 + threadIdx.x;    // [0, NE*CIN*8*4*32)
    int lane = idx & 31;
    int kk   = (idx >> 5) & 3;
    int wp   = (idx >> 7) & 7;
    int c    = (idx >> 10) & 127;
    int e    = idx >> 17;
    int g    = lane >> 2;
    int t4   = lane & 3;
    int olo  = wp * 16 + g;
    int ohi  = olo + 8;
    int tap0 = kk * 16 + 2 * t4;
    const float* Wlo = W1 + ((size_t)(e * COUT + olo) * CIN + c) * KW;
    const float* Whi = W1 + ((size_t)(e * COUT + ohi) * CIN + c) * KW;
    uint4 u;
    u.x = pack_f16x2(Wlo[tap0],     Wlo[tap0 + 1]);
    u.y = pack_f16x2(Whi[tap0],     Whi[tap0 + 1]);
    u.z = pack_f16x2(Wlo[tap0 + 8], Wlo[tap0 + 9]);
    u.w = pack_f16x2(Whi[tap0 + 8], Whi[tap0 + 9]);
    *(uint4*)(g_w1h + (size_t)idx * 4) = u;
}

// ---------------- kernel 1: gate_x = mean over L (warp per row) -----------
__global__ void k_gatex(const float* __restrict__ x) {
    int row  = blockIdx.x * 4 + (threadIdx.x >> 5);   // (b, c) flattened
    int lane = threadIdx.x & 31;
    const float4* xp = (const float4*)(x + (size_t)row * LIN);
    float s = 0.f;
#pragma unroll
    for (int k = 0; k < 8; ++k) {
        float4 v = xp[lane + k * 32];
        s += (v.x + v.y) + (v.z + v.w);
    }
#pragma unroll
    for (int off = 16; off; off >>= 1) s += __shfl_down_sync(0xffffffffu, s, off);
    if (lane == 0) g_gatex[row] = s * (1.0f / (float)LIN);
}

// ---------------- kernel 2: gating, top-k, loss ---------------------------
__device__ __forceinline__ float cv_sq4(const float* w) {
    float mn = 0.25f * (w[0] + w[1] + w[2] + w[3]);
    float s = 0.f;
#pragma unroll
    for (int e = 0; e < 4; ++e) { float d = w[e] - mn; s += d * d; }
    s *= (1.0f / 3.0f);                    // ddof = 1
    return s / (mn * mn + 1e-10f);
}

__global__ void k_gate(const float* __restrict__ noise,
                       const float* __restrict__ w_gate,
                       const float* __restrict__ w_noise,
                       float* __restrict__ out, int loss_idx)
{
    int b = threadIdx.x;                   // 32 threads, one per batch row
    float clean[NE] = {0.f, 0.f, 0.f, 0.f};
    float raw[NE]   = {0.f, 0.f, 0.f, 0.f};
    for (int c = 0; c < CIN; ++c) {
        float gx = g_gatex[b * CIN + c];
#pragma unroll
        for (int e = 0; e < NE; ++e) {
            clean[e] = fmaf(gx, w_gate[c * NE + e],  clean[e]);
            raw[e]   = fmaf(gx, w_noise[c * NE + e], raw[e]);
        }
    }
    float nstd[NE], noisy[NE], sm[NE];
    float m = -1e30f;
#pragma unroll
    for (int e = 0; e < NE; ++e) {
        float r  = raw[e];
        float sp = (r > 20.f) ? r : log1pf(expf(r));   // softplus
        nstd[e]  = sp + 0.01f;                          // NOISE_EPS
        noisy[e] = clean[e] + noise[b * NE + e] * nstd[e];
        m = fmaxf(m, noisy[e]);
    }
    float ssum = 0.f;
#pragma unroll
    for (int e = 0; e < NE; ++e) { sm[e] = expf(noisy[e] - m); ssum += sm[e]; }
    float inv = 1.f / ssum;
#pragma unroll
    for (int e = 0; e < NE; ++e) sm[e] *= inv;

    int   idx[4] = {0, 1, 2, 3};
    float v[4]   = {sm[0], sm[1], sm[2], sm[3]};
#pragma unroll
    for (int a = 0; a < 3; ++a)
#pragma unroll
        for (int q = a + 1; q < 4; ++q)
            if (v[q] > v[a]) {
                float tv = v[a]; v[a] = v[q]; v[q] = tv;
                int   ti = idx[a]; idx[a] = idx[q]; idx[q] = ti;
            }

    float e1 = expf(v[1] - v[0]);
    float gs = 1.f + e1;
    float g0 = 1.f / gs;
    float g1 = e1 / gs;
    g_sel [b * 2 + 0] = idx[0];  g_sel [b * 2 + 1] = idx[1];
    g_selw[b * 2 + 0] = g0;      g_selw[b * 2 + 1] = g1;

    float gates[4] = {0.f, 0.f, 0.f, 0.f};
    gates[idx[0]] = g0;
    gates[idx[1]] = g1;

    float thr_in  = v[2];
    float thr_out = v[1];
    float loadc[4];
#pragma unroll
    for (int e = 0; e < NE; ++e) {
        bool  is_in = noisy[e] > thr_in;
        float thr   = is_in ? thr_in : thr_out;
        float z     = (clean[e] - thr) / nstd[e];
        loadc[e]    = 0.5f * (1.f + erff(z * 0.70710678118654752f));
    }

    float imp[4], ld[4];
#pragma unroll
    for (int e = 0; e < NE; ++e) {
        float a = gates[e], l2 = loadc[e];
        for (int off = 16; off; off >>= 1) {
            a  += __shfl_down_sync(0xffffffffu, a,  off);
            l2 += __shfl_down_sync(0xffffffffu, l2, off);
        }
        imp[e] = a; ld[e] = l2;
    }
    if (b == 0)
        out[loss_idx] = 0.01f * (cv_sq4(imp) + cv_sq4(ld));
}

// ---------------- kernel 3: fp16 tensor-core sparse conv experts ----------
// grid: (NTILES=18, BQ=32) = 576 CTAs, 256 threads (8 warps), 2 CTAs/SM.
// CTA tile: M=128 (Cout) x N=56 (l). Warp w owns m-rows [w*16,+16), full N.
// A register-direct from pre-swizzled g_w1h (R13). B pairs staged per-bb
// CONTIGUOUS rows sxq[ch][bb][j] (stride 20 words: 16B-aligned, phase
// conflict-free) -> 4 LDS.128 per channel replace 14 scattered LDS.32.
// Ping-pong group buffers, 4 channels/group, one barrier/group (R15).
__global__ void __launch_bounds__(256, 2)
k_conv(const float* __restrict__ x,
       const float* __restrict__ b1,
       const float* __restrict__ W2,
       const float* __restrict__ b2,
       float* __restrict__ out)
{
    __shared__ __align__(16) uint32_t sxq[2][BBUF]; // ping-pong B rows, 9KB
    __shared__ float sred[8][4][28];    // epilogue partials
    __shared__ float sz[2][NTILE];
    __shared__ float ysum[2][NTILE];
    __shared__ float sW2[2][COUT];
    __shared__ float sb1[COUT];

    const int b    = blockIdx.y;
    const int l0   = blockIdx.x * NTILE;
    const int tid  = threadIdx.x;
    const int warp = tid >> 5;          // 0..7 = m-group
    const int lane = tid & 31;
    const int g    = lane >> 2;
    const int t4   = lane & 3;
    const int m0   = warp * 16;
    const int rlo  = m0 + g;
    const int rhi  = m0 + g + 8;
    const int bb   = g + 2 * t4;        // B row index, 0..13
    const int rowb = bb * BROW;

    const float* xb = x + (size_t)b * CIN * LIN;

    // staging-entry constants (thread-invariant across groups):
    // entry w = tid + 256*i -> (ch, bb_e, j): stage pack(x[p], x[p+1]),
    // p = bb_e + 8*j <= 117; l0+p+1 <= 896+118 < LIN: no bounds checks.
    int  ech[4], esmo[4], epos[4];
    bool eact[4];
#pragma unroll
    for (int i = 0; i < 4; ++i) {
        int w = tid + 256 * i;
        eact[i] = (w < NENT);
        int ww  = eact[i] ? w : 0;
        int ch  = ww / 196;
        int r   = ww - ch * 196;
        int bbe = r / 14;
        int j   = r - bbe * 14;
        ech[i]  = ch;
        esmo[i] = ch * BCH + bbe * BROW + j;
        epos[i] = bbe + 8 * j;
    }

    if (tid < 2 * NTILE) {
        int t = tid >= NTILE;
        ysum[t][tid - t * NTILE] = 0.f;
    }

    // per-thread A-fragment offset within one (e,c) block: warp/kk/lane
    const size_t a_toff = (((size_t)warp * 4) * 32 + lane) * 4;  // + kk*128

    for (int slot = 0; slot < 2; ++slot) {
        const int   e  = g_sel [b * 2 + slot];
        const float gw = g_selw[b * 2 + slot];
        const uint32_t* Ae = g_w1h + (size_t)e * (CIN * ACH) + a_toff;

        sW2[tid >> 7][tid & 127] = W2[e * 2 * COUT + tid];   // 256 == 2*COUT
        if (tid < COUT) sb1[tid] = b1[e * COUT + tid];

        float acc[7][4];
#pragma unroll
        for (int i = 0; i < 7; ++i)
#pragma unroll
            for (int j = 0; j < 4; ++j) acc[i][j] = 0.f;

        uint4 A_0, A_1, A_2, A_3, B_0, B_1, B_2, B_3;
        float xra[4], xrb[4];

        // ---- pipeline prologue: buf0 <- group0, regs <- group1, A <- ch0 --
        LDX(0);
        STX(0);
        LDX(1);
        LDA(A_0, A_1, A_2, A_3, 0);
        __syncthreads();                // buf0 visible

        // 16 iterations x 8 channels (groups 2k, 2k+1)
        for (int c = 0; c < CIN; c += 8) {
            const int G = c >> 2;       // even group index

            // --- group G (channels c..c+3) from buf0 ---
            STX(1);                     // regs(G+1) -> buf1 (drains at barrier)
            if (c + 8 < CIN) LDX(G + 2);
            LDA(B_0, B_1, B_2, B_3, c + 1);
            mma_channel(acc, A_0, A_1, A_2, A_3, &sxq[0][0 * BCH + rowb]);
            LDA(A_0, A_1, A_2, A_3, c + 2);
            mma_channel(acc, B_0, B_1, B_2, B_3, &sxq[0][1 * BCH + rowb]);
            LDA(B_0, B_1, B_2, B_3, c + 3);
            mma_channel(acc, A_0, A_1, A_2, A_3, &sxq[0][2 * BCH + rowb]);
            LDA(A_0, A_1, A_2, A_3, c + 4);
            mma_channel(acc, B_0, B_1, B_2, B_3, &sxq[0][3 * BCH + rowb]);
            __syncthreads();            // buf1 visible; buf0 free

            // --- group G+1 (channels c+4..c+7) from buf1 ---
            if (c + 8 < CIN) {
                STX(0);                 // regs(G+2) -> buf0
                if (c + 12 < CIN) LDX(G + 3);
            }
            LDA(B_0, B_1, B_2, B_3, c + 5);
            mma_channel(acc, A_0, A_1, A_2, A_3, &sxq[1][0 * BCH + rowb]);
            LDA(A_0, A_1, A_2, A_3, c + 6);
            mma_channel(acc, B_0, B_1, B_2, B_3, &sxq[1][1 * BCH + rowb]);
            LDA(B_0, B_1, B_2, B_3, c + 7);
            mma_channel(acc, A_0, A_1, A_2, A_3, &sxq[1][2 * BCH + rowb]);
            if (c + 8 < CIN) LDA(A_0, A_1, A_2, A_3, c + 8);
            mma_channel(acc, B_0, B_1, B_2, B_3, &sxq[1][3 * BCH + rowb]);
            __syncthreads();            // buf0 visible; buf1 free
        }

        // ---- epilogue: bias + relu + W2 partials, reduce over Cout ----
        float b1lo = sb1[rlo], b1hi = sb1[rhi];
        float w2lo0 = sW2[0][rlo], w2hi0 = sW2[0][rhi];
        float w2lo1 = sW2[1][rlo], w2hi1 = sW2[1][rhi];
        float p[28];                    // [nb*4 + r*2 + t], r = col parity
#pragma unroll
        for (int nb = 0; nb < 7; ++nb) {
            float h00 = fmaxf(acc[nb][0] + b1lo, 0.f);   // (rlo, col even)
            float h01 = fmaxf(acc[nb][1] + b1lo, 0.f);   // (rlo, col odd)
            float h10 = fmaxf(acc[nb][2] + b1hi, 0.f);   // (rhi, col even)
            float h11 = fmaxf(acc[nb][3] + b1hi, 0.f);   // (rhi, col odd)
            p[nb * 4 + 0] = fmaf(w2lo0, h00, w2hi0 * h10);
            p[nb * 4 + 1] = fmaf(w2lo1, h00, w2hi1 * h10);
            p[nb * 4 + 2] = fmaf(w2lo0, h01, w2hi0 * h11);
            p[nb * 4 + 3] = fmaf(w2lo1, h01, w2hi1 * h11);
        }
        // reduce over g (8 lanes sharing t4)
#pragma unroll
        for (int j = 0; j < 28; ++j) {
            p[j] += __shfl_down_sync(0xffffffffu, p[j], 16);
            p[j] += __shfl_down_sync(0xffffffffu, p[j], 8);
            p[j] += __shfl_down_sync(0xffffffffu, p[j], 4);
        }
        __syncthreads();                // sred free from prior use
        if (lane < 4) {
#pragma unroll
            for (int j = 0; j < 28; ++j) sred[warp][lane][j] = p[j];
        }
        __syncthreads();

        // z[t][col]: sum the 8 m-warps
        if (tid < 2 * NTILE) {
            int t   = tid >= NTILE;
            int col = tid - t * NTILE;
            int nb  = col >> 3;
            int tt4 = (col >> 1) & 3;
            int r   = col & 1;
            int pj  = nb * 4 + r * 2 + t;
            float z = b2[e * 2 + t];
#pragma unroll
            for (int w8 = 0; w8 < 8; ++w8) z += sred[w8][tt4][pj];
            sz[t][col] = z;
        }
        __syncthreads();

        // 2-way softmax over t, gate-weighted accumulate
        if (tid < NTILE) {
            float z0 = sz[0][tid], z1 = sz[1][tid];
            float mm = fmaxf(z0, z1);
            float a0 = expf(z0 - mm), a1 = expf(z1 - mm);
            float is = 1.f / (a0 + a1);
            ysum[0][tid] += gw * a0 * is;
            ysum[1][tid] += gw * a1 * is;
        }
        __syncthreads();
    }

    if (tid < 2 * NTILE) {
        int t = tid >= NTILE, l = tid - t * NTILE;
        int gl = l0 + l;
        if (gl < LOUT)
            out[((size_t)b * 2 + t) * LOUT + gl] = ysum[t][l];
    }
}

// ---------------- launcher ------------------------------------------------
extern "C" void kernel_launch(void* const* d_in, const int* in_sizes, int n_in,
                              void* d_out, int out_size)
{
    const float* x       = (const float*)d_in[0];
    const float* noise   = (const float*)d_in[1];
    const float* w_gate  = (const float*)d_in[2];
    const float* w_noise = (const float*)d_in[3];
    const float* W1      = (const float*)d_in[4];
    const float* b1      = (const float*)d_in[5];
    const float* W2      = (const float*)d_in[6];
    const float* b2      = (const float*)d_in[7];
    float* out = (float*)d_out;

    k_wconv<<<NE * CIN * 8 * 4 * 32 / 256, 256>>>(W1);
    k_gatex<<<BQ * CIN / 4, 128>>>(x);
    k_gate<<<1, 32>>>(noise, w_gate, w_noise, out, out_size - 1);
    dim3 grid(NTILES, BQ);
    k_conv<<<grid, 256>>>(x, b1, W2, b2, out);
}